// round 1
// baseline (speedup 1.0000x reference)
#include <cuda_runtime.h>
#include <cstdint>

#define N_NODES 100000
#define N_EDGES 640000
#define HDIM 128
#define H2DIM 256
#define EDIM 16

// ---------------- scratch (device globals: no allocation allowed) ------------
__device__ float g_P  [(size_t)N_NODES * HDIM];   // node_rep @ W1
__device__ float g_Q  [(size_t)N_NODES * HDIM];   // node_rep @ W2
__device__ float g_MSG[(size_t)N_EDGES * HDIM];   // pre-BN messages
__device__ float g_Y  [(size_t)N_NODES * HDIM];   // scatter target
__device__ float g_H1 [(size_t)N_NODES * H2DIM];  // y @ Wm1 (pre-BN)
__device__ float g_H2 [(size_t)N_NODES * H2DIM];  // h1' @ Wm2 (pre-BN)
// BN stat slots: [0,128)=msg, [128,384)=bn1, [384,640)=bn2
__device__ float g_sum[640];
__device__ float g_sq [640];
__device__ float g_scaleArr[640];
__device__ float g_shiftArr[640];

// ---------------- utility kernels -------------------------------------------
__global__ void zero_y_stats_kernel() {
    size_t i = (size_t)blockIdx.x * blockDim.x + threadIdx.x;
    const size_t tot = (size_t)N_NODES * HDIM;
    const size_t stride = (size_t)gridDim.x * blockDim.x;
    for (size_t p = i; p < tot; p += stride) g_Y[p] = 0.f;
    if (i < 640) { g_sum[i] = 0.f; g_sq[i] = 0.f; }
}

__global__ void bn_finalize_kernel(const float* __restrict__ g,
                                   const float* __restrict__ b,
                                   int off, int cols, float invCnt) {
    int c = blockIdx.x * blockDim.x + threadIdx.x;
    if (c < cols) {
        float mean = g_sum[off + c] * invCnt;
        float var  = fmaxf(g_sq[off + c] * invCnt - mean * mean, 0.f);
        float a = g[c] * rsqrtf(var + 1e-5f);
        g_scaleArr[off + c] = a;
        g_shiftArr[off + c] = fmaf(-mean, a, b[c]);
    }
}

// ---------------- generic GEMM with fused BN machinery ----------------------
// C[M,NC] = act(A) @ B  (+ cBias), where act(x) = relu(aScale[k]*x + aShift[k])
// when aScale != null (BN+ReLU of the previous stage fused into the A load).
// If sSum != null, also accumulates per-column sum / sum-of-squares of C
// (block-reduced in smem, then global atomics) for the NEXT BN stage.
__global__ __launch_bounds__(256, 2) void gemm_bn_kernel(
    const float* __restrict__ A, const float* __restrict__ B,
    float* __restrict__ C, int M, int K, int NC,
    const float* __restrict__ aScale, const float* __restrict__ aShift,
    const float* __restrict__ cBias,
    float* __restrict__ sSum, float* __restrict__ sSq)
{
    __shared__ float As[16][132];
    __shared__ float Bs[16][128];
    __shared__ float red[2][128];

    const int tid = threadIdx.x;
    const int tx = tid & 15, ty = tid >> 4;
    const int bm = blockIdx.x * 128;
    const int bn = blockIdx.y * 128;

    float acc[8][8];
#pragma unroll
    for (int i = 0; i < 8; i++)
#pragma unroll
        for (int j = 0; j < 8; j++) acc[i][j] = 0.f;

    for (int k0 = 0; k0 < K; k0 += 16) {
        // A tile (128x16), transposed into smem
#pragma unroll
        for (int l = 0; l < 2; l++) {
            int idx = tid + l * 256;
            int r = idx >> 2, c4 = idx & 3;
            int grow = bm + r;
            float4 v = make_float4(0.f, 0.f, 0.f, 0.f);
            if (grow < M) {
                v = *(const float4*)(A + (size_t)grow * K + k0 + c4 * 4);
                if (aScale) {
                    int kc = k0 + c4 * 4;
                    v.x = fmaxf(fmaf(v.x, aScale[kc + 0], aShift[kc + 0]), 0.f);
                    v.y = fmaxf(fmaf(v.y, aScale[kc + 1], aShift[kc + 1]), 0.f);
                    v.z = fmaxf(fmaf(v.z, aScale[kc + 2], aShift[kc + 2]), 0.f);
                    v.w = fmaxf(fmaf(v.w, aScale[kc + 3], aShift[kc + 3]), 0.f);
                }
            }
            As[c4 * 4 + 0][r] = v.x;
            As[c4 * 4 + 1][r] = v.y;
            As[c4 * 4 + 2][r] = v.z;
            As[c4 * 4 + 3][r] = v.w;
        }
        // B tile (16x128)
#pragma unroll
        for (int l = 0; l < 2; l++) {
            int idx = tid + l * 256;
            int r = idx >> 5, c4 = idx & 31;
            *(float4*)&Bs[r][c4 * 4] =
                *(const float4*)(B + (size_t)(k0 + r) * NC + bn + c4 * 4);
        }
        __syncthreads();
#pragma unroll
        for (int k = 0; k < 16; k++) {
            float a[8], b[8];
            *(float4*)&a[0] = *(const float4*)&As[k][ty * 8];
            *(float4*)&a[4] = *(const float4*)&As[k][ty * 8 + 4];
            *(float4*)&b[0] = *(const float4*)&Bs[k][tx * 8];
            *(float4*)&b[4] = *(const float4*)&Bs[k][tx * 8 + 4];
#pragma unroll
            for (int i = 0; i < 8; i++)
#pragma unroll
                for (int j = 0; j < 8; j++)
                    acc[i][j] = fmaf(a[i], b[j], acc[i][j]);
        }
        __syncthreads();
    }

    // epilogue
    float bias[8];
#pragma unroll
    for (int j = 0; j < 8; j++) bias[j] = cBias ? cBias[bn + tx * 8 + j] : 0.f;

    float psum[8], psq[8];
#pragma unroll
    for (int j = 0; j < 8; j++) { psum[j] = 0.f; psq[j] = 0.f; }

#pragma unroll
    for (int i = 0; i < 8; i++) {
        int grow = bm + ty * 8 + i;
        if (grow < M) {
            float out[8];
#pragma unroll
            for (int j = 0; j < 8; j++) {
                float v = acc[i][j] + bias[j];
                out[j] = v;
                psum[j] += v;
                psq[j]  += v * v;
            }
            *(float4*)(C + (size_t)grow * NC + bn + tx * 8)     = *(float4*)&out[0];
            *(float4*)(C + (size_t)grow * NC + bn + tx * 8 + 4) = *(float4*)&out[4];
        }
    }

    if (sSum) {
        if (tid < 128) { red[0][tid] = 0.f; red[1][tid] = 0.f; }
        __syncthreads();
#pragma unroll
        for (int j = 0; j < 8; j++) {
            atomicAdd(&red[0][tx * 8 + j], psum[j]);
            atomicAdd(&red[1][tx * 8 + j], psq[j]);
        }
        __syncthreads();
        if (tid < 128) {
            atomicAdd(&sSum[bn + tid], red[0][tid]);
            atomicAdd(&sSq [bn + tid], red[1][tid]);
        }
    }
}

// ---------------- edge message kernel ----------------------------------------
// MSG[e] = edge_rep[e] @ W3 + edge_attr[e] @ We + be + P[src[e]] + Q[dst[e]]
// (K=128 main loop + K=16 tail for the edge encoder), plus per-column BN stats.
__global__ __launch_bounds__(256, 2) void edge_msg_kernel(
    const float* __restrict__ edge_rep, const float* __restrict__ edge_attr,
    const int* __restrict__ src, const int* __restrict__ dst,
    const float* __restrict__ W3, const float* __restrict__ We,
    const float* __restrict__ be)
{
    __shared__ float As[16][132];
    __shared__ float Bs[16][128];
    __shared__ float red[2][128];

    const int tid = threadIdx.x;
    const int tx = tid & 15, ty = tid >> 4;
    const size_t bm = (size_t)blockIdx.x * 128;

    float acc[8][8];
#pragma unroll
    for (int i = 0; i < 8; i++)
#pragma unroll
        for (int j = 0; j < 8; j++) acc[i][j] = 0.f;

    for (int kt = 0; kt < 9; kt++) {
        const float* Ap; int lda, kof; const float* Bp;
        if (kt < 8) { Ap = edge_rep;  lda = HDIM; kof = kt * 16; Bp = W3 + (size_t)kt * 16 * HDIM; }
        else        { Ap = edge_attr; lda = EDIM; kof = 0;       Bp = We; }
#pragma unroll
        for (int l = 0; l < 2; l++) {
            int idx = tid + l * 256;
            int r = idx >> 2, c4 = idx & 3;
            float4 v = *(const float4*)(Ap + (bm + r) * lda + kof + c4 * 4);
            As[c4 * 4 + 0][r] = v.x;
            As[c4 * 4 + 1][r] = v.y;
            As[c4 * 4 + 2][r] = v.z;
            As[c4 * 4 + 3][r] = v.w;
        }
#pragma unroll
        for (int l = 0; l < 2; l++) {
            int idx = tid + l * 256;
            int r = idx >> 5, c4 = idx & 31;
            *(float4*)&Bs[r][c4 * 4] = *(const float4*)(Bp + (size_t)r * HDIM + c4 * 4);
        }
        __syncthreads();
#pragma unroll
        for (int k = 0; k < 16; k++) {
            float a[8], b[8];
            *(float4*)&a[0] = *(const float4*)&As[k][ty * 8];
            *(float4*)&a[4] = *(const float4*)&As[k][ty * 8 + 4];
            *(float4*)&b[0] = *(const float4*)&Bs[k][tx * 8];
            *(float4*)&b[4] = *(const float4*)&Bs[k][tx * 8 + 4];
#pragma unroll
            for (int i = 0; i < 8; i++)
#pragma unroll
                for (int j = 0; j < 8; j++)
                    acc[i][j] = fmaf(a[i], b[j], acc[i][j]);
        }
        __syncthreads();
    }

    const int col0 = tx * 8;
    float bev[8];
    *(float4*)&bev[0] = *(const float4*)(be + col0);
    *(float4*)&bev[4] = *(const float4*)(be + col0 + 4);

    float psum[8], psq[8];
#pragma unroll
    for (int j = 0; j < 8; j++) { psum[j] = 0.f; psq[j] = 0.f; }

#pragma unroll
    for (int i = 0; i < 8; i++) {
        size_t e = bm + ty * 8 + i;
        int s = src[e], d = dst[e];
        float pv[8], qv[8], out[8];
        *(float4*)&pv[0] = *(const float4*)(g_P + (size_t)s * HDIM + col0);
        *(float4*)&pv[4] = *(const float4*)(g_P + (size_t)s * HDIM + col0 + 4);
        *(float4*)&qv[0] = *(const float4*)(g_Q + (size_t)d * HDIM + col0);
        *(float4*)&qv[4] = *(const float4*)(g_Q + (size_t)d * HDIM + col0 + 4);
#pragma unroll
        for (int j = 0; j < 8; j++) {
            float v = acc[i][j] + pv[j] + qv[j] + bev[j];
            out[j] = v;
            psum[j] += v;
            psq[j]  += v * v;
        }
        *(float4*)(g_MSG + e * HDIM + col0)     = *(float4*)&out[0];
        *(float4*)(g_MSG + e * HDIM + col0 + 4) = *(float4*)&out[4];
    }

    if (tid < 128) { red[0][tid] = 0.f; red[1][tid] = 0.f; }
    __syncthreads();
#pragma unroll
    for (int j = 0; j < 8; j++) {
        atomicAdd(&red[0][col0 + j], psum[j]);
        atomicAdd(&red[1][col0 + j], psq[j]);
    }
    __syncthreads();
    if (tid < 128) {
        atomicAdd(&g_sum[tid], red[0][tid]);
        atomicAdd(&g_sq [tid], red[1][tid]);
    }
}

// ---------------- BN+ReLU+scatter ---------------------------------------------
__global__ void scatter_kernel(const int* __restrict__ dst) {
    int t = blockIdx.x * blockDim.x + threadIdx.x;
    size_t e = (size_t)((unsigned)t >> 7);
    int c = t & 127;
    if (e < (size_t)N_EDGES) {
        int d = dst[e];
        float v = fmaf(g_MSG[e * HDIM + c], g_scaleArr[c], g_shiftArr[c]);
        v = fmaxf(v, 0.f);
        atomicAdd(&g_Y[(size_t)d * HDIM + c], v);
    }
}

// ---------------- launch ------------------------------------------------------
extern "C" void kernel_launch(void* const* d_in, const int* in_sizes, int n_in,
                              void* d_out, int out_size) {
    const float* node_rep  = (const float*)d_in[0];
    const float* edge_rep  = (const float*)d_in[1];
    const float* edge_attr = (const float*)d_in[2];
    const int*   eidx      = (const int*)d_in[3];
    const float* W1  = (const float*)d_in[4];
    const float* W2  = (const float*)d_in[5];
    const float* W3  = (const float*)d_in[6];
    const float* We  = (const float*)d_in[7];
    const float* be  = (const float*)d_in[8];
    const float* bng = (const float*)d_in[9];
    const float* bnb = (const float*)d_in[10];
    const float* Wm1 = (const float*)d_in[11];
    const float* g1  = (const float*)d_in[12];
    const float* b1  = (const float*)d_in[13];
    const float* Wm2 = (const float*)d_in[14];
    const float* g2  = (const float*)d_in[15];
    const float* b2  = (const float*)d_in[16];
    const float* Wm3 = (const float*)d_in[17];
    const float* bm3 = (const float*)d_in[18];
    float* out = (float*)d_out;

    const int* src = eidx;
    const int* dst = eidx + N_EDGES;

    float *P, *Q, *Y, *H1, *H2, *SUM, *SQ, *SCALE, *SHIFT;
    cudaGetSymbolAddress((void**)&P,  g_P);
    cudaGetSymbolAddress((void**)&Q,  g_Q);
    cudaGetSymbolAddress((void**)&Y,  g_Y);
    cudaGetSymbolAddress((void**)&H1, g_H1);
    cudaGetSymbolAddress((void**)&H2, g_H2);
    cudaGetSymbolAddress((void**)&SUM,   g_sum);
    cudaGetSymbolAddress((void**)&SQ,    g_sq);
    cudaGetSymbolAddress((void**)&SCALE, g_scaleArr);
    cudaGetSymbolAddress((void**)&SHIFT, g_shiftArr);

    const int MBLK = (N_NODES + 127) / 128;  // 782

    zero_y_stats_kernel<<<4096, 256>>>();

    // node linears
    gemm_bn_kernel<<<dim3(MBLK, 1), 256>>>(node_rep, W1, P, N_NODES, HDIM, HDIM,
                                           nullptr, nullptr, nullptr, nullptr, nullptr);
    gemm_bn_kernel<<<dim3(MBLK, 1), 256>>>(node_rep, W2, Q, N_NODES, HDIM, HDIM,
                                           nullptr, nullptr, nullptr, nullptr, nullptr);

    // edge GEMM + encoder + gathers + BN stats
    edge_msg_kernel<<<N_EDGES / 128, 256>>>(edge_rep, edge_attr, src, dst, W3, We, be);

    // msg BN params
    bn_finalize_kernel<<<1, 128>>>(bng, bnb, 0, 128, 1.f / (float)N_EDGES);

    // BN + ReLU + scatter-sum
    scatter_kernel<<<(N_EDGES * HDIM) / 512, 512>>>(dst);

    // MLP layer 1: H1 = Y @ Wm1 (raw), stats -> slot 128
    gemm_bn_kernel<<<dim3(MBLK, 2), 256>>>(Y, Wm1, H1, N_NODES, HDIM, H2DIM,
                                           nullptr, nullptr, nullptr, SUM + 128, SQ + 128);
    bn_finalize_kernel<<<2, 128>>>(g1, b1, 128, 256, 1.f / (float)N_NODES);

    // MLP layer 2: H2 = relu(bn1(H1)) @ Wm2 (raw), stats -> slot 384
    gemm_bn_kernel<<<dim3(MBLK, 2), 256>>>(H1, Wm2, H2, N_NODES, H2DIM, H2DIM,
                                           SCALE + 128, SHIFT + 128, nullptr, SUM + 384, SQ + 384);
    bn_finalize_kernel<<<2, 128>>>(g2, b2, 384, 256, 1.f / (float)N_NODES);

    // MLP layer 3: out = relu(bn2(H2)) @ Wm3 + bm3
    gemm_bn_kernel<<<dim3(MBLK, 1), 256>>>(H2, Wm3, out, N_NODES, H2DIM, HDIM,
                                           SCALE + 384, SHIFT + 384, bm3, nullptr, nullptr);
}

// round 2
// speedup vs baseline: 1.2203x; 1.2203x over previous
#include <cuda_runtime.h>
#include <cstdint>

#define N_NODES 100000
#define N_EDGES 640000
#define HDIM 128
#define H2DIM 256
#define EDIM 16

// ---------------- scratch (device globals: no allocation allowed) ------------
__device__ float g_P  [(size_t)N_NODES * HDIM];   // node_rep @ W1
__device__ float g_Q  [(size_t)N_NODES * HDIM];   // node_rep @ W2
__device__ float g_MSG[(size_t)N_EDGES * HDIM];   // pre-BN messages
__device__ float g_Y  [(size_t)N_NODES * HDIM];   // scatter target
__device__ float g_H1 [(size_t)N_NODES * H2DIM];  // y @ Wm1 (pre-BN)
__device__ float g_H2 [(size_t)N_NODES * H2DIM];  // h1' @ Wm2 (pre-BN)
// BN stat slots: [0,128)=msg, [128,384)=bn1, [384,640)=bn2
__device__ float g_sum[640];
__device__ float g_sq [640];
__device__ float g_scaleArr[640];
__device__ float g_shiftArr[640];

// ---------------- helpers -----------------------------------------------------
__device__ __forceinline__ unsigned f2tf32(float x) {
    unsigned r;
    asm("cvt.rna.tf32.f32 %0, %1;" : "=r"(r) : "f"(x));
    return r;
}

__device__ __forceinline__ void mma_tf32(float* c, const unsigned* a, const unsigned* b) {
    asm volatile(
        "mma.sync.aligned.m16n8k8.row.col.f32.tf32.tf32.f32 "
        "{%0,%1,%2,%3}, {%4,%5,%6,%7}, {%8,%9}, {%0,%1,%2,%3};"
        : "+f"(c[0]), "+f"(c[1]), "+f"(c[2]), "+f"(c[3])
        : "r"(a[0]), "r"(a[1]), "r"(a[2]), "r"(a[3]), "r"(b[0]), "r"(b[1]));
}

// ---------------- utility kernels -------------------------------------------
__global__ void zero_y_stats_kernel() {
    size_t i = (size_t)blockIdx.x * blockDim.x + threadIdx.x;
    const size_t tot = (size_t)N_NODES * HDIM;
    const size_t stride = (size_t)gridDim.x * blockDim.x;
    for (size_t p = i; p < tot; p += stride) g_Y[p] = 0.f;
    if (i < 640) { g_sum[i] = 0.f; g_sq[i] = 0.f; }
}

__global__ void bn_finalize_kernel(const float* __restrict__ g,
                                   const float* __restrict__ b,
                                   int off, int cols, float invCnt) {
    int c = blockIdx.x * blockDim.x + threadIdx.x;
    if (c < cols) {
        float mean = g_sum[off + c] * invCnt;
        float var  = fmaxf(g_sq[off + c] * invCnt - mean * mean, 0.f);
        float a = g[c] * rsqrtf(var + 1e-5f);
        g_scaleArr[off + c] = a;
        g_shiftArr[off + c] = fmaf(-mean, a, b[c]);
    }
}

// ---------------- tf32 MMA GEMM with fused BN machinery ----------------------
// C[M,NC] = act(A) @ B (+cBias); act(x)=relu(aScale[k]*x+aShift[k]) if aScale.
// If sSum != null, accumulates per-column sum / sum-of-squares of C.
// Tile 128x128x32, 256 threads = 8 warps (4 in M x 2 in N), warp tile 32x64.
__global__ __launch_bounds__(256, 2) void gemm_mma_kernel(
    const float* __restrict__ A, const float* __restrict__ B,
    float* __restrict__ C, int M, int K, int NC,
    const float* __restrict__ aScale, const float* __restrict__ aShift,
    const float* __restrict__ cBias,
    float* __restrict__ sSum, float* __restrict__ sSq)
{
    __shared__ unsigned As[32][136];   // [k][m]
    __shared__ unsigned Bs[32][136];   // [k][n]
    __shared__ float red[2][128];

    const int tid  = threadIdx.x;
    const int lane = tid & 31;
    const int warp = tid >> 5;
    const int wm = (warp & 3) * 32;
    const int wn = (warp >> 2) * 64;
    const int bm = blockIdx.x * 128;
    const int bn = blockIdx.y * 128;

    float acc[2][8][4];
#pragma unroll
    for (int mt = 0; mt < 2; mt++)
#pragma unroll
        for (int nt = 0; nt < 8; nt++)
#pragma unroll
            for (int i = 0; i < 4; i++) acc[mt][nt][i] = 0.f;

    for (int k0 = 0; k0 < K; k0 += 32) {
        // A tile 128x32 -> As[k][m] (with optional fused BN+ReLU on A)
#pragma unroll
        for (int l = 0; l < 4; l++) {
            int idx = tid + l * 256;
            int r = idx >> 3, c4 = idx & 7;
            int grow = bm + r;
            float4 v = make_float4(0.f, 0.f, 0.f, 0.f);
            if (grow < M) {
                v = *(const float4*)(A + (size_t)grow * K + k0 + c4 * 4);
                if (aScale) {
                    int kc = k0 + c4 * 4;
                    v.x = fmaxf(fmaf(v.x, aScale[kc + 0], aShift[kc + 0]), 0.f);
                    v.y = fmaxf(fmaf(v.y, aScale[kc + 1], aShift[kc + 1]), 0.f);
                    v.z = fmaxf(fmaf(v.z, aScale[kc + 2], aShift[kc + 2]), 0.f);
                    v.w = fmaxf(fmaf(v.w, aScale[kc + 3], aShift[kc + 3]), 0.f);
                }
            }
            As[c4 * 4 + 0][r] = f2tf32(v.x);
            As[c4 * 4 + 1][r] = f2tf32(v.y);
            As[c4 * 4 + 2][r] = f2tf32(v.z);
            As[c4 * 4 + 3][r] = f2tf32(v.w);
        }
        // B tile 32x128 -> Bs[k][n]
#pragma unroll
        for (int l = 0; l < 4; l++) {
            int idx = tid + l * 256;
            int r = idx >> 5, c4 = idx & 31;
            float4 v = *(const float4*)(B + (size_t)(k0 + r) * NC + bn + c4 * 4);
            uint4 u;
            u.x = f2tf32(v.x); u.y = f2tf32(v.y); u.z = f2tf32(v.z); u.w = f2tf32(v.w);
            *(uint4*)&Bs[r][c4 * 4] = u;
        }
        __syncthreads();
#pragma unroll
        for (int kk = 0; kk < 32; kk += 8) {
            unsigned af[2][4], bf[8][2];
            const int kr = kk + (lane & 3);
#pragma unroll
            for (int mt = 0; mt < 2; mt++) {
                int m = wm + mt * 16 + (lane >> 2);
                af[mt][0] = As[kr    ][m];
                af[mt][1] = As[kr    ][m + 8];
                af[mt][2] = As[kr + 4][m];
                af[mt][3] = As[kr + 4][m + 8];
            }
#pragma unroll
            for (int nt = 0; nt < 8; nt++) {
                int n = wn + nt * 8 + (lane >> 2);
                bf[nt][0] = Bs[kr    ][n];
                bf[nt][1] = Bs[kr + 4][n];
            }
#pragma unroll
            for (int mt = 0; mt < 2; mt++)
#pragma unroll
                for (int nt = 0; nt < 8; nt++)
                    mma_tf32(acc[mt][nt], af[mt], bf[nt]);
        }
        __syncthreads();
    }

    // ---------------- epilogue ----------------
    float psum[8][2], psq[8][2];
#pragma unroll
    for (int nt = 0; nt < 8; nt++) {
        psum[nt][0] = psum[nt][1] = 0.f;
        psq[nt][0] = psq[nt][1] = 0.f;
    }

#pragma unroll
    for (int nt = 0; nt < 8; nt++) {
        int cl = wn + nt * 8 + 2 * (lane & 3);       // block-local col
        float bx = 0.f, by = 0.f;
        if (cBias) { float2 bb = *(const float2*)(cBias + bn + cl); bx = bb.x; by = bb.y; }
#pragma unroll
        for (int mt = 0; mt < 2; mt++) {
            int R0 = bm + wm + mt * 16 + (lane >> 2);
#pragma unroll
            for (int half = 0; half < 2; half++) {
                int R = R0 + half * 8;
                if (R < M) {
                    float v0 = acc[mt][nt][half * 2 + 0] + bx;
                    float v1 = acc[mt][nt][half * 2 + 1] + by;
                    float2 o; o.x = v0; o.y = v1;
                    *(float2*)(C + (size_t)R * NC + bn + cl) = o;
                    psum[nt][0] += v0; psum[nt][1] += v1;
                    psq[nt][0]  += v0 * v0; psq[nt][1] += v1 * v1;
                }
            }
        }
    }

    if (sSum) {
        if (tid < 128) { red[0][tid] = 0.f; red[1][tid] = 0.f; }
        __syncthreads();
#pragma unroll
        for (int nt = 0; nt < 8; nt++) {
            int cl = wn + nt * 8 + 2 * (lane & 3);
            atomicAdd(&red[0][cl],     psum[nt][0]);
            atomicAdd(&red[0][cl + 1], psum[nt][1]);
            atomicAdd(&red[1][cl],     psq[nt][0]);
            atomicAdd(&red[1][cl + 1], psq[nt][1]);
        }
        __syncthreads();
        if (tid < 128) {
            atomicAdd(&sSum[bn + tid], red[0][tid]);
            atomicAdd(&sSq [bn + tid], red[1][tid]);
        }
    }
}

// ---------------- edge message kernel (tf32 MMA) -------------------------------
// MSG[e] = edge_rep[e]@W3 + edge_attr[e]@We + be + P[src[e]] + Q[dst[e]], + stats
__global__ __launch_bounds__(256, 2) void edge_msg_kernel(
    const float* __restrict__ edge_rep, const float* __restrict__ edge_attr,
    const int* __restrict__ src, const int* __restrict__ dst,
    const float* __restrict__ W3, const float* __restrict__ We,
    const float* __restrict__ be)
{
    __shared__ unsigned As[32][136];
    __shared__ unsigned Bs[32][136];
    __shared__ float red[2][128];

    const int tid  = threadIdx.x;
    const int lane = tid & 31;
    const int warp = tid >> 5;
    const int wm = (warp & 3) * 32;
    const int wn = (warp >> 2) * 64;
    const size_t bm = (size_t)blockIdx.x * 128;

    float acc[2][8][4];
#pragma unroll
    for (int mt = 0; mt < 2; mt++)
#pragma unroll
        for (int nt = 0; nt < 8; nt++)
#pragma unroll
            for (int i = 0; i < 4; i++) acc[mt][nt][i] = 0.f;

    for (int kt = 0; kt < 5; kt++) {
        if (kt < 4) {
            const int kof = kt * 32;
#pragma unroll
            for (int l = 0; l < 4; l++) {
                int idx = tid + l * 256;
                int r = idx >> 3, c4 = idx & 7;
                float4 v = *(const float4*)(edge_rep + (bm + r) * HDIM + kof + c4 * 4);
                As[c4 * 4 + 0][r] = f2tf32(v.x);
                As[c4 * 4 + 1][r] = f2tf32(v.y);
                As[c4 * 4 + 2][r] = f2tf32(v.z);
                As[c4 * 4 + 3][r] = f2tf32(v.w);
            }
#pragma unroll
            for (int l = 0; l < 4; l++) {
                int idx = tid + l * 256;
                int r = idx >> 5, c4 = idx & 31;
                float4 v = *(const float4*)(W3 + (size_t)(kof + r) * HDIM + c4 * 4);
                uint4 u;
                u.x = f2tf32(v.x); u.y = f2tf32(v.y); u.z = f2tf32(v.z); u.w = f2tf32(v.w);
                *(uint4*)&Bs[r][c4 * 4] = u;
            }
        } else {
            // edge encoder tail: K=16
#pragma unroll
            for (int l = 0; l < 2; l++) {
                int idx = tid + l * 256;
                int r = idx >> 2, c4 = idx & 3;
                float4 v = *(const float4*)(edge_attr + (bm + r) * EDIM + c4 * 4);
                As[c4 * 4 + 0][r] = f2tf32(v.x);
                As[c4 * 4 + 1][r] = f2tf32(v.y);
                As[c4 * 4 + 2][r] = f2tf32(v.z);
                As[c4 * 4 + 3][r] = f2tf32(v.w);
            }
#pragma unroll
            for (int l = 0; l < 2; l++) {
                int idx = tid + l * 256;
                int r = idx >> 5, c4 = idx & 31;
                float4 v = *(const float4*)(We + (size_t)r * HDIM + c4 * 4);
                uint4 u;
                u.x = f2tf32(v.x); u.y = f2tf32(v.y); u.z = f2tf32(v.z); u.w = f2tf32(v.w);
                *(uint4*)&Bs[r][c4 * 4] = u;
            }
        }
        __syncthreads();
        const int kmax = (kt < 4) ? 32 : 16;
        for (int kk = 0; kk < kmax; kk += 8) {
            unsigned af[2][4], bf[8][2];
            const int kr = kk + (lane & 3);
#pragma unroll
            for (int mt = 0; mt < 2; mt++) {
                int m = wm + mt * 16 + (lane >> 2);
                af[mt][0] = As[kr    ][m];
                af[mt][1] = As[kr    ][m + 8];
                af[mt][2] = As[kr + 4][m];
                af[mt][3] = As[kr + 4][m + 8];
            }
#pragma unroll
            for (int nt = 0; nt < 8; nt++) {
                int n = wn + nt * 8 + (lane >> 2);
                bf[nt][0] = Bs[kr    ][n];
                bf[nt][1] = Bs[kr + 4][n];
            }
#pragma unroll
            for (int mt = 0; mt < 2; mt++)
#pragma unroll
                for (int nt = 0; nt < 8; nt++)
                    mma_tf32(acc[mt][nt], af[mt], bf[nt]);
        }
        __syncthreads();
    }

    // ---------------- epilogue: gathers + bias + store + stats ----------------
    float psum[8][2], psq[8][2];
#pragma unroll
    for (int nt = 0; nt < 8; nt++) {
        psum[nt][0] = psum[nt][1] = 0.f;
        psq[nt][0] = psq[nt][1] = 0.f;
    }

#pragma unroll
    for (int mt = 0; mt < 2; mt++) {
#pragma unroll
        for (int half = 0; half < 2; half++) {
            size_t e = bm + wm + mt * 16 + (lane >> 2) + half * 8;
            int s = src[e], d = dst[e];
            const float* Prow = g_P + (size_t)s * HDIM;
            const float* Qrow = g_Q + (size_t)d * HDIM;
#pragma unroll
            for (int nt = 0; nt < 8; nt++) {
                int cl = wn + nt * 8 + 2 * (lane & 3);
                float2 pv = *(const float2*)(Prow + cl);
                float2 qv = *(const float2*)(Qrow + cl);
                float2 bb = *(const float2*)(be + cl);
                float v0 = acc[mt][nt][half * 2 + 0] + pv.x + qv.x + bb.x;
                float v1 = acc[mt][nt][half * 2 + 1] + pv.y + qv.y + bb.y;
                float2 o; o.x = v0; o.y = v1;
                *(float2*)(g_MSG + e * HDIM + cl) = o;
                psum[nt][0] += v0; psum[nt][1] += v1;
                psq[nt][0]  += v0 * v0; psq[nt][1] += v1 * v1;
            }
        }
    }

    if (tid < 128) { red[0][tid] = 0.f; red[1][tid] = 0.f; }
    __syncthreads();
#pragma unroll
    for (int nt = 0; nt < 8; nt++) {
        int cl = wn + nt * 8 + 2 * (lane & 3);
        atomicAdd(&red[0][cl],     psum[nt][0]);
        atomicAdd(&red[0][cl + 1], psum[nt][1]);
        atomicAdd(&red[1][cl],     psq[nt][0]);
        atomicAdd(&red[1][cl + 1], psq[nt][1]);
    }
    __syncthreads();
    if (tid < 128) {
        atomicAdd(&g_sum[tid], red[0][tid]);
        atomicAdd(&g_sq [tid], red[1][tid]);
    }
}

// ---------------- BN+ReLU+scatter with vector red ------------------------------
__global__ void scatter_kernel(const int* __restrict__ dst) {
    unsigned t = blockIdx.x * blockDim.x + threadIdx.x;
    size_t e = (size_t)(t >> 5);
    int c4 = (t & 31) * 4;
    if (e < (size_t)N_EDGES) {
        int d = dst[e];
        float4 m = *(const float4*)(g_MSG + e * HDIM + c4);
        float v0 = fmaxf(fmaf(m.x, g_scaleArr[c4 + 0], g_shiftArr[c4 + 0]), 0.f);
        float v1 = fmaxf(fmaf(m.y, g_scaleArr[c4 + 1], g_shiftArr[c4 + 1]), 0.f);
        float v2 = fmaxf(fmaf(m.z, g_scaleArr[c4 + 2], g_shiftArr[c4 + 2]), 0.f);
        float v3 = fmaxf(fmaf(m.w, g_scaleArr[c4 + 3], g_shiftArr[c4 + 3]), 0.f);
        float* p = g_Y + (size_t)d * HDIM + c4;
        asm volatile("red.global.add.v4.f32 [%0], {%1,%2,%3,%4};"
                     :: "l"(p), "f"(v0), "f"(v1), "f"(v2), "f"(v3) : "memory");
    }
}

// ---------------- launch ------------------------------------------------------
extern "C" void kernel_launch(void* const* d_in, const int* in_sizes, int n_in,
                              void* d_out, int out_size) {
    const float* node_rep  = (const float*)d_in[0];
    const float* edge_rep  = (const float*)d_in[1];
    const float* edge_attr = (const float*)d_in[2];
    const int*   eidx      = (const int*)d_in[3];
    const float* W1  = (const float*)d_in[4];
    const float* W2  = (const float*)d_in[5];
    const float* W3  = (const float*)d_in[6];
    const float* We  = (const float*)d_in[7];
    const float* be  = (const float*)d_in[8];
    const float* bng = (const float*)d_in[9];
    const float* bnb = (const float*)d_in[10];
    const float* Wm1 = (const float*)d_in[11];
    const float* g1  = (const float*)d_in[12];
    const float* b1  = (const float*)d_in[13];
    const float* Wm2 = (const float*)d_in[14];
    const float* g2  = (const float*)d_in[15];
    const float* b2  = (const float*)d_in[16];
    const float* Wm3 = (const float*)d_in[17];
    const float* bm3 = (const float*)d_in[18];
    float* out = (float*)d_out;

    const int* src = eidx;
    const int* dst = eidx + N_EDGES;

    float *P, *Q, *Y, *H1, *H2, *SUM, *SQ, *SCALE, *SHIFT;
    cudaGetSymbolAddress((void**)&P,  g_P);
    cudaGetSymbolAddress((void**)&Q,  g_Q);
    cudaGetSymbolAddress((void**)&Y,  g_Y);
    cudaGetSymbolAddress((void**)&H1, g_H1);
    cudaGetSymbolAddress((void**)&H2, g_H2);
    cudaGetSymbolAddress((void**)&SUM,   g_sum);
    cudaGetSymbolAddress((void**)&SQ,    g_sq);
    cudaGetSymbolAddress((void**)&SCALE, g_scaleArr);
    cudaGetSymbolAddress((void**)&SHIFT, g_shiftArr);

    const int MBLK = (N_NODES + 127) / 128;  // 782

    zero_y_stats_kernel<<<4096, 256>>>();

    // node linears (tf32 MMA)
    gemm_mma_kernel<<<dim3(MBLK, 1), 256>>>(node_rep, W1, P, N_NODES, HDIM, HDIM,
                                            nullptr, nullptr, nullptr, nullptr, nullptr);
    gemm_mma_kernel<<<dim3(MBLK, 1), 256>>>(node_rep, W2, Q, N_NODES, HDIM, HDIM,
                                            nullptr, nullptr, nullptr, nullptr, nullptr);

    // edge GEMM + encoder + gathers + BN stats
    edge_msg_kernel<<<N_EDGES / 128, 256>>>(edge_rep, edge_attr, src, dst, W3, We, be);

    // msg BN params
    bn_finalize_kernel<<<1, 128>>>(bng, bnb, 0, 128, 1.f / (float)N_EDGES);

    // BN + ReLU + scatter-sum (vector red)
    scatter_kernel<<<(N_EDGES * 32) / 256, 256>>>(dst);

    // MLP layer 1
    gemm_mma_kernel<<<dim3(MBLK, 2), 256>>>(Y, Wm1, H1, N_NODES, HDIM, H2DIM,
                                            nullptr, nullptr, nullptr, SUM + 128, SQ + 128);
    bn_finalize_kernel<<<2, 128>>>(g1, b1, 128, 256, 1.f / (float)N_NODES);

    // MLP layer 2
    gemm_mma_kernel<<<dim3(MBLK, 2), 256>>>(H1, Wm2, H2, N_NODES, H2DIM, H2DIM,
                                            SCALE + 128, SHIFT + 128, nullptr, SUM + 384, SQ + 384);
    bn_finalize_kernel<<<2, 128>>>(g2, b2, 384, 256, 1.f / (float)N_NODES);

    // MLP layer 3
    gemm_mma_kernel<<<dim3(MBLK, 1), 256>>>(H2, Wm3, out, N_NODES, H2DIM, HDIM,
                                            SCALE + 384, SHIFT + 384, bm3, nullptr, nullptr);
}

// round 3
// speedup vs baseline: 1.5261x; 1.2505x over previous
#include <cuda_runtime.h>
#include <cstdint>

#define N_NODES 100000
#define N_EDGES 640000
#define HDIM 128
#define H2DIM 256
#define EDIM 16

// ---------------- scratch (device globals) ------------------------------------
__device__ float g_PQ [(size_t)N_NODES * 256];    // [node][0:128]=node@W1, [128:256]=node@W2
__device__ float g_MSG[(size_t)N_EDGES * HDIM];   // pre-BN messages
__device__ float g_Y  [(size_t)N_NODES * HDIM];   // scatter target
__device__ float g_H1 [(size_t)N_NODES * H2DIM];
__device__ float g_H2 [(size_t)N_NODES * H2DIM];
// BN stat slots: [0,128)=msg, [128,384)=bn1, [384,640)=bn2
__device__ float g_sum[640];
__device__ float g_sq [640];
__device__ float g_scaleArr[640];
__device__ float g_shiftArr[640];

// packed tf32 weights
#define OFF_NODE 0        // [128][256]  W1 | W2
#define OFF_EDGE 32768    // [144][128]  W3 rows 0..127, We rows 128..143
#define OFF_M1   51200    // [128][256]
#define OFF_M2   83968    // [256][256]
#define OFF_M3   149504   // [256][128]
#define W_TOTAL  182272
__device__ unsigned g_Wbuf[W_TOTAL];

// ---------------- helpers ------------------------------------------------------
__device__ __forceinline__ unsigned f2tf32(float x) {
    unsigned r;
    asm("cvt.rna.tf32.f32 %0, %1;" : "=r"(r) : "f"(x));
    return r;
}

__device__ __forceinline__ void mma_tf32(float* c, const unsigned* a, const unsigned* b) {
    asm volatile(
        "mma.sync.aligned.m16n8k8.row.col.f32.tf32.tf32.f32 "
        "{%0,%1,%2,%3}, {%4,%5,%6,%7}, {%8,%9}, {%0,%1,%2,%3};"
        : "+f"(c[0]), "+f"(c[1]), "+f"(c[2]), "+f"(c[3])
        : "r"(a[0]), "r"(a[1]), "r"(a[2]), "r"(a[3]), "r"(b[0]), "r"(b[1]));
}

__device__ __forceinline__ void cp16(uint32_t dst, const void* src, bool pred) {
    int sz = pred ? 16 : 0;
    asm volatile("cp.async.cg.shared.global [%0], [%1], 16, %2;"
                 :: "r"(dst), "l"(src), "r"(sz));
}
__device__ __forceinline__ void cp_commit() { asm volatile("cp.async.commit_group;"); }
template <int N> __device__ __forceinline__ void cp_wait() {
    asm volatile("cp.async.wait_group %0;" :: "n"(N));
}
__device__ __forceinline__ uint32_t s2u(const void* p) {
    uint32_t a;
    asm("{ .reg .u64 t; cvta.to.shared.u64 t, %1; cvt.u32.u64 %0, t; }" : "=r"(a) : "l"(p));
    return a;
}

// ---------------- utility kernels ----------------------------------------------
__global__ void prep_kernel(const float* __restrict__ W1, const float* __restrict__ W2,
                            const float* __restrict__ W3, const float* __restrict__ We,
                            const float* __restrict__ Wm1, const float* __restrict__ Wm2,
                            const float* __restrict__ Wm3) {
    int i = blockIdx.x * blockDim.x + threadIdx.x;
    if (i < 32768) {
        int k = i >> 8, n = i & 255;
        float v = (n < 128) ? W1[k * 128 + n] : W2[k * 128 + (n - 128)];
        g_Wbuf[OFF_NODE + i] = f2tf32(v);
    } else if (i < 51200) {
        int j = i - 32768;
        float v = (j < 128 * 128) ? W3[j] : We[j - 128 * 128];
        g_Wbuf[OFF_EDGE + j] = f2tf32(v);
    } else if (i < 83968) {
        g_Wbuf[OFF_M1 + (i - 51200)] = f2tf32(Wm1[i - 51200]);
    } else if (i < 149504) {
        g_Wbuf[OFF_M2 + (i - 83968)] = f2tf32(Wm2[i - 83968]);
    } else if (i < W_TOTAL) {
        g_Wbuf[OFF_M3 + (i - 149504)] = f2tf32(Wm3[i - 149504]);
    }
}

__global__ void zero_y_stats_kernel() {
    size_t i = (size_t)blockIdx.x * blockDim.x + threadIdx.x;
    const size_t tot = (size_t)N_NODES * HDIM;
    const size_t stride = (size_t)gridDim.x * blockDim.x;
    for (size_t p = i; p < tot; p += stride) g_Y[p] = 0.f;
    if (i < 640) { g_sum[i] = 0.f; g_sq[i] = 0.f; }
}

__global__ void bn_finalize_kernel(const float* __restrict__ g,
                                   const float* __restrict__ b,
                                   int off, int cols, float invCnt) {
    int c = blockIdx.x * blockDim.x + threadIdx.x;
    if (c < cols) {
        float mean = g_sum[off + c] * invCnt;
        float var  = fmaxf(g_sq[off + c] * invCnt - mean * mean, 0.f);
        float a = g[c] * rsqrtf(var + 1e-5f);
        g_scaleArr[off + c] = a;
        g_shiftArr[off + c] = fmaf(-mean, a, b[c]);
    }
}

// ---------------- pipelined tf32 GEMM with fused BN ---------------------------
// C[M,NC] = act(A) @ Wu (+cBias); act = relu(aScale[k]*x+aShift[k]) if aScale.
// Wu is pre-converted tf32 bits [K][NC]. cp.async 2-stage pipeline.
// Tile 128x128x32. 256 threads = 8 warps (4 M x 2 N), warp tile 32x64.
extern __shared__ char smem_raw[];

__global__ void __launch_bounds__(256, 2) gemm_mma_kernel(
    const float* __restrict__ A, const unsigned* __restrict__ Wu,
    float* __restrict__ C, int M, int K, int NC,
    const float* __restrict__ aScale, const float* __restrict__ aShift,
    const float* __restrict__ cBias,
    float* __restrict__ sSum, float* __restrict__ sSq)
{
    typedef float    AsT[128][36];
    typedef unsigned BsT[32][136];
    AsT* As = reinterpret_cast<AsT*>(smem_raw);                    // 2*128*36*4 = 36864
    BsT* Bs = reinterpret_cast<BsT*>(smem_raw + 36864);            // 2*32*136*4 = 34816
    float* scs  = (float*)(smem_raw + 36864 + 34816);              // 256
    float* shs  = scs + 256;                                       // 256
    float* red0 = shs + 256;                                       // 128
    float* red1 = red0 + 128;                                      // 128

    const int tid = threadIdx.x, lane = tid & 31, warp = tid >> 5;
    const int wm = (warp & 3) * 32, wn = (warp >> 2) * 64;
    const int bm = blockIdx.x * 128, bn = blockIdx.y * 128;
    const bool useBN = (aScale != nullptr);

    const uint32_t AsAddr = s2u(smem_raw);
    const uint32_t BsAddr = AsAddr + 36864;

    if (useBN && tid < K) { scs[tid] = aScale[tid]; shs[tid] = aShift[tid]; }

    auto issue_copy = [&](int t) {
        const int s = t & 1;
        const int k0 = t * 32;
#pragma unroll
        for (int l = 0; l < 4; l++) {
            int c = tid + l * 256;
            int row = c >> 3, cc = c & 7;
            int grow = bm + row;
            const float* src = A + (size_t)grow * K + k0 + cc * 4;
            uint32_t dst = AsAddr + (uint32_t)(((s * 128 + row) * 36 + cc * 4) * 4);
            cp16(dst, src, grow < M);
        }
#pragma unroll
        for (int l = 0; l < 4; l++) {
            int c = tid + l * 256;
            int row = c >> 5, cc = c & 31;
            const unsigned* src = Wu + (size_t)(k0 + row) * NC + bn + cc * 4;
            uint32_t dst = BsAddr + (uint32_t)(((s * 32 + row) * 136 + cc * 4) * 4);
            cp16(dst, src, true);
        }
        cp_commit();
    };

    float acc[2][8][4];
#pragma unroll
    for (int mt = 0; mt < 2; mt++)
#pragma unroll
        for (int nt = 0; nt < 8; nt++)
#pragma unroll
            for (int i = 0; i < 4; i++) acc[mt][nt][i] = 0.f;

    const int T = K >> 5;
    issue_copy(0);

    for (int t = 0; t < T; t++) {
        if (t + 1 < T) { issue_copy(t + 1); cp_wait<1>(); }
        else           { cp_wait<0>(); }
        __syncthreads();
        const int s = t & 1;
        const int k0 = t * 32;
#pragma unroll
        for (int q = 0; q < 4; q++) {
            const int kr = q * 8 + (lane & 3);
            float s0 = 1.f, h0 = 0.f, s4 = 1.f, h4 = 0.f;
            if (useBN) {
                s0 = scs[k0 + kr];     h0 = shs[k0 + kr];
                s4 = scs[k0 + kr + 4]; h4 = shs[k0 + kr + 4];
            }
            unsigned af[2][4], bf[8][2];
#pragma unroll
            for (int mt = 0; mt < 2; mt++) {
                int m = wm + mt * 16 + (lane >> 2);
                float a0 = As[s][m][kr],     a1 = As[s][m + 8][kr];
                float a2 = As[s][m][kr + 4], a3 = As[s][m + 8][kr + 4];
                if (useBN) {
                    a0 = fmaxf(fmaf(a0, s0, h0), 0.f);
                    a1 = fmaxf(fmaf(a1, s0, h0), 0.f);
                    a2 = fmaxf(fmaf(a2, s4, h4), 0.f);
                    a3 = fmaxf(fmaf(a3, s4, h4), 0.f);
                }
                af[mt][0] = f2tf32(a0); af[mt][1] = f2tf32(a1);
                af[mt][2] = f2tf32(a2); af[mt][3] = f2tf32(a3);
            }
#pragma unroll
            for (int nt = 0; nt < 8; nt++) {
                int n = wn + nt * 8 + (lane >> 2);
                bf[nt][0] = Bs[s][kr][n];
                bf[nt][1] = Bs[s][kr + 4][n];
            }
#pragma unroll
            for (int mt = 0; mt < 2; mt++)
#pragma unroll
                for (int nt = 0; nt < 8; nt++)
                    mma_tf32(acc[mt][nt], af[mt], bf[nt]);
        }
        __syncthreads();
    }

    // ---------------- epilogue ----------------
    float psum[8][2], psq[8][2];
#pragma unroll
    for (int nt = 0; nt < 8; nt++) {
        psum[nt][0] = psum[nt][1] = 0.f;
        psq[nt][0] = psq[nt][1] = 0.f;
    }

#pragma unroll
    for (int nt = 0; nt < 8; nt++) {
        int cl = wn + nt * 8 + 2 * (lane & 3);
        float bx = 0.f, by = 0.f;
        if (cBias) { float2 bb = *(const float2*)(cBias + bn + cl); bx = bb.x; by = bb.y; }
#pragma unroll
        for (int mt = 0; mt < 2; mt++) {
            int R0 = bm + wm + mt * 16 + (lane >> 2);
#pragma unroll
            for (int half = 0; half < 2; half++) {
                int R = R0 + half * 8;
                if (R < M) {
                    float v0 = acc[mt][nt][half * 2 + 0] + bx;
                    float v1 = acc[mt][nt][half * 2 + 1] + by;
                    float2 o; o.x = v0; o.y = v1;
                    *(float2*)(C + (size_t)R * NC + bn + cl) = o;
                    psum[nt][0] += v0; psum[nt][1] += v1;
                    psq[nt][0]  += v0 * v0; psq[nt][1] += v1 * v1;
                }
            }
        }
    }

    if (sSum) {
        if (tid < 128) { red0[tid] = 0.f; red1[tid] = 0.f; }
        __syncthreads();
#pragma unroll
        for (int nt = 0; nt < 8; nt++) {
            int cl = wn + nt * 8 + 2 * (lane & 3);
            atomicAdd(&red0[cl],     psum[nt][0]);
            atomicAdd(&red0[cl + 1], psum[nt][1]);
            atomicAdd(&red1[cl],     psq[nt][0]);
            atomicAdd(&red1[cl + 1], psq[nt][1]);
        }
        __syncthreads();
        if (tid < 128) {
            atomicAdd(&sSum[bn + tid], red0[tid]);
            atomicAdd(&sSq [bn + tid], red1[tid]);
        }
    }
}

// ---------------- pipelined edge message kernel -------------------------------
// MSG[e] = edge_rep[e]@W3 + edge_attr[e]@We + be + P[src[e]] + Q[dst[e]], + stats
__global__ void __launch_bounds__(256, 2) edge_msg_kernel(
    const float* __restrict__ edge_rep, const float* __restrict__ edge_attr,
    const int* __restrict__ src, const int* __restrict__ dst,
    const float* __restrict__ be)
{
    typedef float    AsT[128][36];
    typedef unsigned BsT[32][136];
    AsT* As = reinterpret_cast<AsT*>(smem_raw);
    BsT* Bs = reinterpret_cast<BsT*>(smem_raw + 36864);
    float* red0 = (float*)(smem_raw + 36864 + 34816);
    float* red1 = red0 + 128;

    const int tid = threadIdx.x, lane = tid & 31, warp = tid >> 5;
    const int wm = (warp & 3) * 32, wn = (warp >> 2) * 64;
    const size_t bm = (size_t)blockIdx.x * 128;

    const uint32_t AsAddr = s2u(smem_raw);
    const uint32_t BsAddr = AsAddr + 36864;
    const unsigned* Wu = g_Wbuf + OFF_EDGE;

    // L2 prefetch of the P/Q gather rows (hides gather latency behind mainloop)
    {
        int e0 = (int)bm + (tid >> 1);
        const float* row = (tid & 1) ? (g_PQ + (size_t)dst[e0] * 256 + 128)
                                     : (g_PQ + (size_t)src[e0] * 256);
#pragma unroll
        for (int j = 0; j < 4; j++)
            asm volatile("prefetch.global.L2 [%0];" :: "l"(row + j * 32));
    }

    auto issue_copy = [&](int t) {
        const int s = t & 1;
        if (t < 4) {
            const int k0 = t * 32;
#pragma unroll
            for (int l = 0; l < 4; l++) {
                int c = tid + l * 256;
                int row = c >> 3, cc = c & 7;
                const float* sp = edge_rep + (bm + row) * HDIM + k0 + cc * 4;
                uint32_t dp = AsAddr + (uint32_t)(((s * 128 + row) * 36 + cc * 4) * 4);
                cp16(dp, sp, true);
            }
#pragma unroll
            for (int l = 0; l < 4; l++) {
                int c = tid + l * 256;
                int row = c >> 5, cc = c & 31;
                const unsigned* sp = Wu + (size_t)(k0 + row) * HDIM + cc * 4;
                uint32_t dp = BsAddr + (uint32_t)(((s * 32 + row) * 136 + cc * 4) * 4);
                cp16(dp, sp, true);
            }
        } else {
#pragma unroll
            for (int l = 0; l < 2; l++) {
                int c = tid + l * 256;
                int row = c >> 2, cc = c & 3;
                const float* sp = edge_attr + (bm + row) * EDIM + cc * 4;
                uint32_t dp = AsAddr + (uint32_t)(((s * 128 + row) * 36 + cc * 4) * 4);
                cp16(dp, sp, true);
            }
#pragma unroll
            for (int l = 0; l < 2; l++) {
                int c = tid + l * 256;
                int row = c >> 5, cc = c & 31;
                const unsigned* sp = Wu + (size_t)(128 + row) * HDIM + cc * 4;
                uint32_t dp = BsAddr + (uint32_t)(((s * 32 + row) * 136 + cc * 4) * 4);
                cp16(dp, sp, true);
            }
        }
        cp_commit();
    };

    float acc[2][8][4];
#pragma unroll
    for (int mt = 0; mt < 2; mt++)
#pragma unroll
        for (int nt = 0; nt < 8; nt++)
#pragma unroll
            for (int i = 0; i < 4; i++) acc[mt][nt][i] = 0.f;

    issue_copy(0);

    for (int t = 0; t < 5; t++) {
        if (t + 1 < 5) { issue_copy(t + 1); cp_wait<1>(); }
        else           { cp_wait<0>(); }
        __syncthreads();
        const int s = t & 1;
        const int qmax = (t < 4) ? 4 : 2;
        for (int q = 0; q < qmax; q++) {
            const int kr = q * 8 + (lane & 3);
            unsigned af[2][4], bf[8][2];
#pragma unroll
            for (int mt = 0; mt < 2; mt++) {
                int m = wm + mt * 16 + (lane >> 2);
                af[mt][0] = f2tf32(As[s][m][kr]);
                af[mt][1] = f2tf32(As[s][m + 8][kr]);
                af[mt][2] = f2tf32(As[s][m][kr + 4]);
                af[mt][3] = f2tf32(As[s][m + 8][kr + 4]);
            }
#pragma unroll
            for (int nt = 0; nt < 8; nt++) {
                int n = wn + nt * 8 + (lane >> 2);
                bf[nt][0] = Bs[s][kr][n];
                bf[nt][1] = Bs[s][kr + 4][n];
            }
#pragma unroll
            for (int mt = 0; mt < 2; mt++)
#pragma unroll
                for (int nt = 0; nt < 8; nt++)
                    mma_tf32(acc[mt][nt], af[mt], bf[nt]);
        }
        __syncthreads();
    }

    // ---------------- epilogue: gathers + bias + store + stats ----------------
    float psum[8][2], psq[8][2];
#pragma unroll
    for (int nt = 0; nt < 8; nt++) {
        psum[nt][0] = psum[nt][1] = 0.f;
        psq[nt][0] = psq[nt][1] = 0.f;
    }

#pragma unroll
    for (int mt = 0; mt < 2; mt++) {
#pragma unroll
        for (int half = 0; half < 2; half++) {
            size_t e = bm + wm + mt * 16 + (lane >> 2) + half * 8;
            int s = src[e], d = dst[e];
            const float* Prow = g_PQ + (size_t)s * 256;
            const float* Qrow = g_PQ + (size_t)d * 256 + 128;
#pragma unroll
            for (int nt = 0; nt < 8; nt++) {
                int cl = wn + nt * 8 + 2 * (lane & 3);
                float2 pv = *(const float2*)(Prow + cl);
                float2 qv = *(const float2*)(Qrow + cl);
                float2 bb = *(const float2*)(be + cl);
                float v0 = acc[mt][nt][half * 2 + 0] + pv.x + qv.x + bb.x;
                float v1 = acc[mt][nt][half * 2 + 1] + pv.y + qv.y + bb.y;
                float2 o; o.x = v0; o.y = v1;
                *(float2*)(g_MSG + e * HDIM + cl) = o;
                psum[nt][0] += v0; psum[nt][1] += v1;
                psq[nt][0]  += v0 * v0; psq[nt][1] += v1 * v1;
            }
        }
    }

    if (tid < 128) { red0[tid] = 0.f; red1[tid] = 0.f; }
    __syncthreads();
#pragma unroll
    for (int nt = 0; nt < 8; nt++) {
        int cl = wn + nt * 8 + 2 * (lane & 3);
        atomicAdd(&red0[cl],     psum[nt][0]);
        atomicAdd(&red0[cl + 1], psum[nt][1]);
        atomicAdd(&red1[cl],     psq[nt][0]);
        atomicAdd(&red1[cl + 1], psq[nt][1]);
    }
    __syncthreads();
    if (tid < 128) {
        atomicAdd(&g_sum[tid], red0[tid]);
        atomicAdd(&g_sq [tid], red1[tid]);
    }
}

// ---------------- BN+ReLU+scatter with vector red ------------------------------
__global__ void scatter_kernel(const int* __restrict__ dst) {
    unsigned t = blockIdx.x * blockDim.x + threadIdx.x;
    size_t e = (size_t)(t >> 5);
    int c4 = (t & 31) * 4;
    if (e < (size_t)N_EDGES) {
        int d = dst[e];
        float4 m = *(const float4*)(g_MSG + e * HDIM + c4);
        float v0 = fmaxf(fmaf(m.x, g_scaleArr[c4 + 0], g_shiftArr[c4 + 0]), 0.f);
        float v1 = fmaxf(fmaf(m.y, g_scaleArr[c4 + 1], g_shiftArr[c4 + 1]), 0.f);
        float v2 = fmaxf(fmaf(m.z, g_scaleArr[c4 + 2], g_shiftArr[c4 + 2]), 0.f);
        float v3 = fmaxf(fmaf(m.w, g_scaleArr[c4 + 3], g_shiftArr[c4 + 3]), 0.f);
        float* p = g_Y + (size_t)d * HDIM + c4;
        asm volatile("red.global.add.v4.f32 [%0], {%1,%2,%3,%4};"
                     :: "l"(p), "f"(v0), "f"(v1), "f"(v2), "f"(v3) : "memory");
    }
}

// ---------------- launch ------------------------------------------------------
extern "C" void kernel_launch(void* const* d_in, const int* in_sizes, int n_in,
                              void* d_out, int out_size) {
    const float* node_rep  = (const float*)d_in[0];
    const float* edge_rep  = (const float*)d_in[1];
    const float* edge_attr = (const float*)d_in[2];
    const int*   eidx      = (const int*)d_in[3];
    const float* W1  = (const float*)d_in[4];
    const float* W2  = (const float*)d_in[5];
    const float* W3  = (const float*)d_in[6];
    const float* We  = (const float*)d_in[7];
    const float* be  = (const float*)d_in[8];
    const float* bng = (const float*)d_in[9];
    const float* bnb = (const float*)d_in[10];
    const float* Wm1 = (const float*)d_in[11];
    const float* g1  = (const float*)d_in[12];
    const float* b1  = (const float*)d_in[13];
    const float* Wm2 = (const float*)d_in[14];
    const float* g2  = (const float*)d_in[15];
    const float* b2  = (const float*)d_in[16];
    const float* Wm3 = (const float*)d_in[17];
    const float* bm3 = (const float*)d_in[18];
    float* out = (float*)d_out;

    const int* src = eidx;
    const int* dst = eidx + N_EDGES;

    float *PQ, *Y, *H1, *H2, *SUM, *SQ, *SCALE, *SHIFT;
    unsigned* WB;
    cudaGetSymbolAddress((void**)&PQ, g_PQ);
    cudaGetSymbolAddress((void**)&Y,  g_Y);
    cudaGetSymbolAddress((void**)&H1, g_H1);
    cudaGetSymbolAddress((void**)&H2, g_H2);
    cudaGetSymbolAddress((void**)&SUM,   g_sum);
    cudaGetSymbolAddress((void**)&SQ,    g_sq);
    cudaGetSymbolAddress((void**)&SCALE, g_scaleArr);
    cudaGetSymbolAddress((void**)&SHIFT, g_shiftArr);
    cudaGetSymbolAddress((void**)&WB, g_Wbuf);

    const int GEMM_SMEM = 36864 + 34816 + 2048 + 1024;   // 74752
    const int EDGE_SMEM = 36864 + 34816 + 1024;          // 72704
    cudaFuncSetAttribute(gemm_mma_kernel, cudaFuncAttributeMaxDynamicSharedMemorySize, GEMM_SMEM);
    cudaFuncSetAttribute(edge_msg_kernel, cudaFuncAttributeMaxDynamicSharedMemorySize, EDGE_SMEM);

    const int MBLK = (N_NODES + 127) / 128;  // 782

    prep_kernel<<<(W_TOTAL + 255) / 256, 256>>>(W1, W2, W3, We, Wm1, Wm2, Wm3);
    zero_y_stats_kernel<<<4096, 256>>>();

    // fused node linears: PQ = node_rep @ [W1|W2]
    gemm_mma_kernel<<<dim3(MBLK, 2), 256, GEMM_SMEM>>>(
        node_rep, WB + OFF_NODE, PQ, N_NODES, HDIM, 256,
        nullptr, nullptr, nullptr, nullptr, nullptr);

    // edge GEMM + encoder + gathers + BN stats
    edge_msg_kernel<<<N_EDGES / 128, 256, EDGE_SMEM>>>(edge_rep, edge_attr, src, dst, be);

    bn_finalize_kernel<<<1, 128>>>(bng, bnb, 0, 128, 1.f / (float)N_EDGES);

    // BN + ReLU + scatter-sum
    scatter_kernel<<<(N_EDGES * 32) / 256, 256>>>(dst);

    // MLP layer 1
    gemm_mma_kernel<<<dim3(MBLK, 2), 256, GEMM_SMEM>>>(
        Y, WB + OFF_M1, H1, N_NODES, HDIM, H2DIM,
        nullptr, nullptr, nullptr, SUM + 128, SQ + 128);
    bn_finalize_kernel<<<2, 128>>>(g1, b1, 128, 256, 1.f / (float)N_NODES);

    // MLP layer 2
    gemm_mma_kernel<<<dim3(MBLK, 2), 256, GEMM_SMEM>>>(
        H1, WB + OFF_M2, H2, N_NODES, H2DIM, H2DIM,
        SCALE + 128, SHIFT + 128, nullptr, SUM + 384, SQ + 384);
    bn_finalize_kernel<<<2, 128>>>(g2, b2, 384, 256, 1.f / (float)N_NODES);

    // MLP layer 3
    gemm_mma_kernel<<<dim3(MBLK, 1), 256, GEMM_SMEM>>>(
        H2, WB + OFF_M3, out, N_NODES, H2DIM, HDIM,
        SCALE + 384, SHIFT + 384, bm3, nullptr, nullptr);
}

// round 4
// speedup vs baseline: 2.5412x; 1.6652x over previous
#include <cuda_runtime.h>
#include <cstdint>

#define N_NODES 100000
#define N_EDGES 640000
#define HDIM 128
#define H2DIM 256
#define EDIM 16

// ---------------- scratch (device globals) ------------------------------------
__device__ float g_PQ [(size_t)N_NODES * 256];    // [node][0:128]=node@W1, [128:256]=node@W2
__device__ float g_MSG[(size_t)N_EDGES * HDIM];   // pre-BN messages
__device__ float g_Y  [(size_t)N_NODES * HDIM];   // scatter target
__device__ float g_H1 [(size_t)N_NODES * H2DIM];
__device__ float g_H2 [(size_t)N_NODES * H2DIM];
// BN stat slots: [0,128)=msg, [128,384)=bn1, [384,640)=bn2
__device__ float g_sum[640];
__device__ float g_sq [640];
__device__ float g_scaleArr[640];
__device__ float g_shiftArr[640];

// packed tf32 weights
#define OFF_NODE 0        // [128][256]  W1 | W2
#define OFF_EDGE 32768    // [144][128]  W3 rows 0..127, We rows 128..143
#define OFF_M1   51200    // [128][256]
#define OFF_M2   83968    // [256][256]
#define OFF_M3   149504   // [256][128]
#define W_TOTAL  182272
__device__ unsigned g_Wbuf[W_TOTAL];

// ---------------- helpers ------------------------------------------------------
__device__ __forceinline__ unsigned f2tf32(float x) {
    unsigned r;
    asm("cvt.rna.tf32.f32 %0, %1;" : "=r"(r) : "f"(x));
    return r;
}

__device__ __forceinline__ void mma_tf32(float* c, const unsigned* a, const unsigned* b) {
    asm volatile(
        "mma.sync.aligned.m16n8k8.row.col.f32.tf32.tf32.f32 "
        "{%0,%1,%2,%3}, {%4,%5,%6,%7}, {%8,%9}, {%0,%1,%2,%3};"
        : "+f"(c[0]), "+f"(c[1]), "+f"(c[2]), "+f"(c[3])
        : "r"(a[0]), "r"(a[1]), "r"(a[2]), "r"(a[3]), "r"(b[0]), "r"(b[1]));
}

__device__ __forceinline__ void cp16(uint32_t dst, const void* src, bool pred) {
    int sz = pred ? 16 : 0;
    asm volatile("cp.async.cg.shared.global [%0], [%1], 16, %2;"
                 :: "r"(dst), "l"(src), "r"(sz));
}
__device__ __forceinline__ void cp_commit() { asm volatile("cp.async.commit_group;"); }
template <int N> __device__ __forceinline__ void cp_wait() {
    asm volatile("cp.async.wait_group %0;" :: "n"(N));
}
__device__ __forceinline__ uint32_t s2u(const void* p) {
    uint32_t a;
    asm("{ .reg .u64 t; cvta.to.shared.u64 t, %1; cvt.u32.u64 %0, t; }" : "=r"(a) : "l"(p));
    return a;
}

// smem geometry (bytes)
#define AS_STAGE  18432             // 128*36*4
#define BS_STAGE  17408             // 32*136*4
#define AS_BYTES  (3 * AS_STAGE)    // 55296
#define BS_BYTES  (3 * BS_STAGE)    // 52224
#define PIPE_BYTES (AS_BYTES + BS_BYTES)  // 107520

// ---------------- utility kernels ----------------------------------------------
__global__ void prep_kernel(const float* __restrict__ W1, const float* __restrict__ W2,
                            const float* __restrict__ W3, const float* __restrict__ We,
                            const float* __restrict__ Wm1, const float* __restrict__ Wm2,
                            const float* __restrict__ Wm3) {
    int i = blockIdx.x * blockDim.x + threadIdx.x;
    if (i < 32768) {
        int k = i >> 8, n = i & 255;
        float v = (n < 128) ? W1[k * 128 + n] : W2[k * 128 + (n - 128)];
        g_Wbuf[OFF_NODE + i] = f2tf32(v);
    } else if (i < 51200) {
        int j = i - 32768;
        float v = (j < 128 * 128) ? W3[j] : We[j - 128 * 128];
        g_Wbuf[OFF_EDGE + j] = f2tf32(v);
    } else if (i < 83968) {
        g_Wbuf[OFF_M1 + (i - 51200)] = f2tf32(Wm1[i - 51200]);
    } else if (i < 149504) {
        g_Wbuf[OFF_M2 + (i - 83968)] = f2tf32(Wm2[i - 83968]);
    } else if (i < W_TOTAL) {
        g_Wbuf[OFF_M3 + (i - 149504)] = f2tf32(Wm3[i - 149504]);
    }
}

__global__ void zero_y_stats_kernel() {
    size_t i = (size_t)blockIdx.x * blockDim.x + threadIdx.x;
    const size_t tot = (size_t)N_NODES * HDIM;
    const size_t stride = (size_t)gridDim.x * blockDim.x;
    for (size_t p = i; p < tot; p += stride) g_Y[p] = 0.f;
    if (i < 640) { g_sum[i] = 0.f; g_sq[i] = 0.f; }
}

__global__ void bn_finalize_kernel(const float* __restrict__ g,
                                   const float* __restrict__ b,
                                   int off, int cols, float invCnt) {
    int c = blockIdx.x * blockDim.x + threadIdx.x;
    if (c < cols) {
        float mean = g_sum[off + c] * invCnt;
        float var  = fmaxf(g_sq[off + c] * invCnt - mean * mean, 0.f);
        float a = g[c] * rsqrtf(var + 1e-5f);
        g_scaleArr[off + c] = a;
        g_shiftArr[off + c] = fmaf(-mean, a, b[c]);
    }
}

extern __shared__ char smem_raw[];

// ---------------- 3-stage pipelined tf32 GEMM with fused BN -------------------
// C[M,NC] = act(A) @ Wu (+cBias); act = relu(aScale[k]*x+aShift[k]) if aScale.
// Epilogue stages acc -> smem, then warp-per-row coalesced float4 stores + stats.
__global__ void __launch_bounds__(256, 2) gemm_mma_kernel(
    const float* __restrict__ A, const unsigned* __restrict__ Wu,
    float* __restrict__ C, int M, int K, int NC,
    const float* __restrict__ aScale, const float* __restrict__ aShift,
    const float* __restrict__ cBias,
    float* __restrict__ sSum, float* __restrict__ sSq)
{
    float    (*As)[128][36]  = reinterpret_cast<float(*)[128][36]>(smem_raw);
    unsigned (*Bs)[32][136]  = reinterpret_cast<unsigned(*)[32][136]>(smem_raw + AS_BYTES);
    float    (*Cs)[132]      = reinterpret_cast<float(*)[132]>(smem_raw);   // overlay
    float* scs  = (float*)(smem_raw + PIPE_BYTES);      // 256
    float* shs  = scs + 256;                            // 256
    float* red0 = shs + 256;                            // 128
    float* red1 = red0 + 128;                           // 128

    const int tid = threadIdx.x, lane = tid & 31, warp = tid >> 5;
    const int wm = (warp & 3) * 32, wn = (warp >> 2) * 64;
    const int bm = blockIdx.x * 128, bn = blockIdx.y * 128;
    const bool useBN = (aScale != nullptr);

    const uint32_t AsAddr = s2u(smem_raw);
    const uint32_t BsAddr = AsAddr + AS_BYTES;

    if (useBN && tid < K) { scs[tid] = aScale[tid]; shs[tid] = aShift[tid]; }

    auto issue_copy = [&](int t) {
        const int s = t % 3;
        const int k0 = t * 32;
#pragma unroll
        for (int l = 0; l < 4; l++) {
            int c = tid + l * 256;
            int row = c >> 3, cc = c & 7;
            int grow = bm + row;
            const float* src = A + (size_t)grow * K + k0 + cc * 4;
            uint32_t dst = AsAddr + (uint32_t)(s * AS_STAGE + (row * 36 + cc * 4) * 4);
            cp16(dst, src, grow < M);
        }
#pragma unroll
        for (int l = 0; l < 4; l++) {
            int c = tid + l * 256;
            int row = c >> 5, cc = c & 31;
            const unsigned* src = Wu + (size_t)(k0 + row) * NC + bn + cc * 4;
            uint32_t dst = BsAddr + (uint32_t)(s * BS_STAGE + (row * 136 + cc * 4) * 4);
            cp16(dst, src, true);
        }
        cp_commit();
    };

    float acc[2][8][4];
#pragma unroll
    for (int mt = 0; mt < 2; mt++)
#pragma unroll
        for (int nt = 0; nt < 8; nt++)
#pragma unroll
            for (int i = 0; i < 4; i++) acc[mt][nt][i] = 0.f;

    const int T = K >> 5;
    issue_copy(0);
    if (T > 1) issue_copy(1);

    for (int t = 0; t < T; t++) {
        if (t + 2 < T)      { issue_copy(t + 2); cp_wait<2>(); }
        else if (t + 1 < T) { cp_wait<1>(); }
        else                { cp_wait<0>(); }
        __syncthreads();
        const int s = t % 3;
        const int k0 = t * 32;
#pragma unroll
        for (int q = 0; q < 4; q++) {
            const int kr = q * 8 + (lane & 3);
            float s0 = 1.f, h0 = 0.f, s4 = 1.f, h4 = 0.f;
            if (useBN) {
                s0 = scs[k0 + kr];     h0 = shs[k0 + kr];
                s4 = scs[k0 + kr + 4]; h4 = shs[k0 + kr + 4];
            }
            unsigned af[2][4], bf[8][2];
#pragma unroll
            for (int mt = 0; mt < 2; mt++) {
                int m = wm + mt * 16 + (lane >> 2);
                float a0 = As[s][m][kr],     a1 = As[s][m + 8][kr];
                float a2 = As[s][m][kr + 4], a3 = As[s][m + 8][kr + 4];
                if (useBN) {
                    a0 = fmaxf(fmaf(a0, s0, h0), 0.f);
                    a1 = fmaxf(fmaf(a1, s0, h0), 0.f);
                    a2 = fmaxf(fmaf(a2, s4, h4), 0.f);
                    a3 = fmaxf(fmaf(a3, s4, h4), 0.f);
                }
                af[mt][0] = f2tf32(a0); af[mt][1] = f2tf32(a1);
                af[mt][2] = f2tf32(a2); af[mt][3] = f2tf32(a3);
            }
#pragma unroll
            for (int nt = 0; nt < 8; nt++) {
                int n = wn + nt * 8 + (lane >> 2);
                bf[nt][0] = Bs[s][kr][n];
                bf[nt][1] = Bs[s][kr + 4][n];
            }
#pragma unroll
            for (int mt = 0; mt < 2; mt++)
#pragma unroll
                for (int nt = 0; nt < 8; nt++)
                    mma_tf32(acc[mt][nt], af[mt], bf[nt]);
        }
        __syncthreads();
    }

    // ---------------- epilogue: stage -> smem, warp-per-row coalesced ----------
#pragma unroll
    for (int mt = 0; mt < 2; mt++)
#pragma unroll
        for (int half = 0; half < 2; half++) {
            int r = wm + mt * 16 + (lane >> 2) + half * 8;
#pragma unroll
            for (int nt = 0; nt < 8; nt++) {
                int cl = wn + nt * 8 + 2 * (lane & 3);
                float2 v; v.x = acc[mt][nt][half * 2 + 0]; v.y = acc[mt][nt][half * 2 + 1];
                *(float2*)&Cs[r][cl] = v;
            }
        }
    if (sSum && tid < 128) { red0[tid] = 0.f; red1[tid] = 0.f; }
    __syncthreads();

    float4 bias = make_float4(0.f, 0.f, 0.f, 0.f);
    if (cBias) bias = *(const float4*)(cBias + bn + lane * 4);
    float psum[4] = {0.f, 0.f, 0.f, 0.f}, psq[4] = {0.f, 0.f, 0.f, 0.f};

#pragma unroll
    for (int i = 0; i < 16; i++) {
        int r = warp * 16 + i;
        int R = bm + r;
        if (R < M) {
            float4 v = *(const float4*)&Cs[r][lane * 4];
            v.x += bias.x; v.y += bias.y; v.z += bias.z; v.w += bias.w;
            *(float4*)(C + (size_t)R * NC + bn + lane * 4) = v;
            psum[0] += v.x; psum[1] += v.y; psum[2] += v.z; psum[3] += v.w;
            psq[0] += v.x * v.x; psq[1] += v.y * v.y;
            psq[2] += v.z * v.z; psq[3] += v.w * v.w;
        }
    }

    if (sSum) {
        __syncthreads();
#pragma unroll
        for (int j = 0; j < 4; j++) {
            atomicAdd(&red0[lane * 4 + j], psum[j]);
            atomicAdd(&red1[lane * 4 + j], psq[j]);
        }
        __syncthreads();
        if (tid < 128) {
            atomicAdd(&sSum[bn + tid], red0[tid]);
            atomicAdd(&sSq [bn + tid], red1[tid]);
        }
    }
}

// ---------------- pipelined edge message kernel -------------------------------
// MSG[e] = edge_rep[e]@W3 + edge_attr[e]@We + be + P[src[e]] + Q[dst[e]], + stats
__global__ void __launch_bounds__(256, 2) edge_msg_kernel(
    const float* __restrict__ edge_rep, const float* __restrict__ edge_attr,
    const int* __restrict__ src, const int* __restrict__ dst,
    const float* __restrict__ be)
{
    float    (*As)[128][36] = reinterpret_cast<float(*)[128][36]>(smem_raw);
    unsigned (*Bs)[32][136] = reinterpret_cast<unsigned(*)[32][136]>(smem_raw + AS_BYTES);
    float    (*Cs)[132]     = reinterpret_cast<float(*)[132]>(smem_raw);   // overlay
    float* red0 = (float*)(smem_raw + PIPE_BYTES);
    float* red1 = red0 + 128;

    const int tid = threadIdx.x, lane = tid & 31, warp = tid >> 5;
    const int wm = (warp & 3) * 32, wn = (warp >> 2) * 64;
    const size_t bm = (size_t)blockIdx.x * 128;

    const uint32_t AsAddr = s2u(smem_raw);
    const uint32_t BsAddr = AsAddr + AS_BYTES;
    const unsigned* Wu = g_Wbuf + OFF_EDGE;

    // L2 prefetch of the P/Q gather rows (hidden behind mainloop)
    {
        int e0 = (int)bm + (tid >> 1);
        const float* row = (tid & 1) ? (g_PQ + (size_t)dst[e0] * 256 + 128)
                                     : (g_PQ + (size_t)src[e0] * 256);
#pragma unroll
        for (int j = 0; j < 4; j++)
            asm volatile("prefetch.global.L2 [%0];" :: "l"(row + j * 32));
    }

    auto issue_copy = [&](int t) {
        const int s = t % 3;
        if (t < 4) {
            const int k0 = t * 32;
#pragma unroll
            for (int l = 0; l < 4; l++) {
                int c = tid + l * 256;
                int row = c >> 3, cc = c & 7;
                const float* sp = edge_rep + (bm + row) * HDIM + k0 + cc * 4;
                uint32_t dp = AsAddr + (uint32_t)(s * AS_STAGE + (row * 36 + cc * 4) * 4);
                cp16(dp, sp, true);
            }
#pragma unroll
            for (int l = 0; l < 4; l++) {
                int c = tid + l * 256;
                int row = c >> 5, cc = c & 31;
                const unsigned* sp = Wu + (size_t)(k0 + row) * HDIM + cc * 4;
                uint32_t dp = BsAddr + (uint32_t)(s * BS_STAGE + (row * 136 + cc * 4) * 4);
                cp16(dp, sp, true);
            }
        } else {
#pragma unroll
            for (int l = 0; l < 2; l++) {
                int c = tid + l * 256;
                int row = c >> 2, cc = c & 3;
                const float* sp = edge_attr + (bm + row) * EDIM + cc * 4;
                uint32_t dp = AsAddr + (uint32_t)(s * AS_STAGE + (row * 36 + cc * 4) * 4);
                cp16(dp, sp, true);
            }
#pragma unroll
            for (int l = 0; l < 2; l++) {
                int c = tid + l * 256;
                int row = c >> 5, cc = c & 31;
                const unsigned* sp = Wu + (size_t)(128 + row) * HDIM + cc * 4;
                uint32_t dp = BsAddr + (uint32_t)(s * BS_STAGE + (row * 136 + cc * 4) * 4);
                cp16(dp, sp, true);
            }
        }
        cp_commit();
    };

    float acc[2][8][4];
#pragma unroll
    for (int mt = 0; mt < 2; mt++)
#pragma unroll
        for (int nt = 0; nt < 8; nt++)
#pragma unroll
            for (int i = 0; i < 4; i++) acc[mt][nt][i] = 0.f;

    issue_copy(0);
    issue_copy(1);

    for (int t = 0; t < 5; t++) {
        if (t + 2 < 5)      { issue_copy(t + 2); cp_wait<2>(); }
        else if (t + 1 < 5) { cp_wait<1>(); }
        else                { cp_wait<0>(); }
        __syncthreads();
        const int s = t % 3;
        const int qmax = (t < 4) ? 4 : 2;
        for (int q = 0; q < qmax; q++) {
            const int kr = q * 8 + (lane & 3);
            unsigned af[2][4], bf[8][2];
#pragma unroll
            for (int mt = 0; mt < 2; mt++) {
                int m = wm + mt * 16 + (lane >> 2);
                af[mt][0] = f2tf32(As[s][m][kr]);
                af[mt][1] = f2tf32(As[s][m + 8][kr]);
                af[mt][2] = f2tf32(As[s][m][kr + 4]);
                af[mt][3] = f2tf32(As[s][m + 8][kr + 4]);
            }
#pragma unroll
            for (int nt = 0; nt < 8; nt++) {
                int n = wn + nt * 8 + (lane >> 2);
                bf[nt][0] = Bs[s][kr][n];
                bf[nt][1] = Bs[s][kr + 4][n];
            }
#pragma unroll
            for (int mt = 0; mt < 2; mt++)
#pragma unroll
                for (int nt = 0; nt < 8; nt++)
                    mma_tf32(acc[mt][nt], af[mt], bf[nt]);
        }
        __syncthreads();
    }

    // ---------------- epilogue: stage -> smem, warp-per-edge coalesced ---------
#pragma unroll
    for (int mt = 0; mt < 2; mt++)
#pragma unroll
        for (int half = 0; half < 2; half++) {
            int r = wm + mt * 16 + (lane >> 2) + half * 8;
#pragma unroll
            for (int nt = 0; nt < 8; nt++) {
                int cl = wn + nt * 8 + 2 * (lane & 3);
                float2 v; v.x = acc[mt][nt][half * 2 + 0]; v.y = acc[mt][nt][half * 2 + 1];
                *(float2*)&Cs[r][cl] = v;
            }
        }
    if (tid < 128) { red0[tid] = 0.f; red1[tid] = 0.f; }
    __syncthreads();

    float4 bev = *(const float4*)(be + lane * 4);
    float psum[4] = {0.f, 0.f, 0.f, 0.f}, psq[4] = {0.f, 0.f, 0.f, 0.f};

#pragma unroll
    for (int i = 0; i < 16; i++) {
        int r = warp * 16 + i;
        size_t e = bm + r;
        int s = src[e], d = dst[e];
        float4 pv = *(const float4*)(g_PQ + (size_t)s * 256 + lane * 4);
        float4 qv = *(const float4*)(g_PQ + (size_t)d * 256 + 128 + lane * 4);
        float4 v = *(const float4*)&Cs[r][lane * 4];
        v.x += pv.x + qv.x + bev.x;
        v.y += pv.y + qv.y + bev.y;
        v.z += pv.z + qv.z + bev.z;
        v.w += pv.w + qv.w + bev.w;
        *(float4*)(g_MSG + e * HDIM + lane * 4) = v;
        psum[0] += v.x; psum[1] += v.y; psum[2] += v.z; psum[3] += v.w;
        psq[0] += v.x * v.x; psq[1] += v.y * v.y;
        psq[2] += v.z * v.z; psq[3] += v.w * v.w;
    }

    __syncthreads();
#pragma unroll
    for (int j = 0; j < 4; j++) {
        atomicAdd(&red0[lane * 4 + j], psum[j]);
        atomicAdd(&red1[lane * 4 + j], psq[j]);
    }
    __syncthreads();
    if (tid < 128) {
        atomicAdd(&g_sum[tid], red0[tid]);
        atomicAdd(&g_sq [tid], red1[tid]);
    }
}

// ---------------- BN+ReLU+scatter with vector red ------------------------------
__global__ void scatter_kernel(const int* __restrict__ dst) {
    unsigned t = blockIdx.x * blockDim.x + threadIdx.x;
    size_t e = (size_t)(t >> 5);
    int c4 = (t & 31) * 4;
    if (e < (size_t)N_EDGES) {
        int d = dst[e];
        float4 m = *(const float4*)(g_MSG + e * HDIM + c4);
        float v0 = fmaxf(fmaf(m.x, g_scaleArr[c4 + 0], g_shiftArr[c4 + 0]), 0.f);
        float v1 = fmaxf(fmaf(m.y, g_scaleArr[c4 + 1], g_shiftArr[c4 + 1]), 0.f);
        float v2 = fmaxf(fmaf(m.z, g_scaleArr[c4 + 2], g_shiftArr[c4 + 2]), 0.f);
        float v3 = fmaxf(fmaf(m.w, g_scaleArr[c4 + 3], g_shiftArr[c4 + 3]), 0.f);
        float* p = g_Y + (size_t)d * HDIM + c4;
        asm volatile("red.global.add.v4.f32 [%0], {%1,%2,%3,%4};"
                     :: "l"(p), "f"(v0), "f"(v1), "f"(v2), "f"(v3) : "memory");
    }
}

// ---------------- launch ------------------------------------------------------
extern "C" void kernel_launch(void* const* d_in, const int* in_sizes, int n_in,
                              void* d_out, int out_size) {
    const float* node_rep  = (const float*)d_in[0];
    const float* edge_rep  = (const float*)d_in[1];
    const float* edge_attr = (const float*)d_in[2];
    const int*   eidx      = (const int*)d_in[3];
    const float* W1  = (const float*)d_in[4];
    const float* W2  = (const float*)d_in[5];
    const float* W3  = (const float*)d_in[6];
    const float* We  = (const float*)d_in[7];
    const float* be  = (const float*)d_in[8];
    const float* bng = (const float*)d_in[9];
    const float* bnb = (const float*)d_in[10];
    const float* Wm1 = (const float*)d_in[11];
    const float* g1  = (const float*)d_in[12];
    const float* b1  = (const float*)d_in[13];
    const float* Wm2 = (const float*)d_in[14];
    const float* g2  = (const float*)d_in[15];
    const float* b2  = (const float*)d_in[16];
    const float* Wm3 = (const float*)d_in[17];
    const float* bm3 = (const float*)d_in[18];
    float* out = (float*)d_out;

    const int* src = eidx;
    const int* dst = eidx + N_EDGES;

    float *PQ, *Y, *H1, *H2, *SUM, *SQ, *SCALE, *SHIFT;
    unsigned* WB;
    cudaGetSymbolAddress((void**)&PQ, g_PQ);
    cudaGetSymbolAddress((void**)&Y,  g_Y);
    cudaGetSymbolAddress((void**)&H1, g_H1);
    cudaGetSymbolAddress((void**)&H2, g_H2);
    cudaGetSymbolAddress((void**)&SUM,   g_sum);
    cudaGetSymbolAddress((void**)&SQ,    g_sq);
    cudaGetSymbolAddress((void**)&SCALE, g_scaleArr);
    cudaGetSymbolAddress((void**)&SHIFT, g_shiftArr);
    cudaGetSymbolAddress((void**)&WB, g_Wbuf);

    const int GEMM_SMEM = PIPE_BYTES + 2048 + 1024;   // 110592
    const int EDGE_SMEM = PIPE_BYTES + 1024;          // 108544
    cudaFuncSetAttribute(gemm_mma_kernel, cudaFuncAttributeMaxDynamicSharedMemorySize, GEMM_SMEM);
    cudaFuncSetAttribute(edge_msg_kernel, cudaFuncAttributeMaxDynamicSharedMemorySize, EDGE_SMEM);

    const int MBLK = (N_NODES + 127) / 128;  // 782

    prep_kernel<<<(W_TOTAL + 255) / 256, 256>>>(W1, W2, W3, We, Wm1, Wm2, Wm3);
    zero_y_stats_kernel<<<4096, 256>>>();

    // fused node linears: PQ = node_rep @ [W1|W2]
    gemm_mma_kernel<<<dim3(MBLK, 2), 256, GEMM_SMEM>>>(
        node_rep, WB + OFF_NODE, PQ, N_NODES, HDIM, 256,
        nullptr, nullptr, nullptr, nullptr, nullptr);

    // edge GEMM + encoder + gathers + BN stats
    edge_msg_kernel<<<N_EDGES / 128, 256, EDGE_SMEM>>>(edge_rep, edge_attr, src, dst, be);

    bn_finalize_kernel<<<1, 128>>>(bng, bnb, 0, 128, 1.f / (float)N_EDGES);

    // BN + ReLU + scatter-sum
    scatter_kernel<<<(N_EDGES * 32) / 256, 256>>>(dst);

    // MLP layer 1
    gemm_mma_kernel<<<dim3(MBLK, 2), 256, GEMM_SMEM>>>(
        Y, WB + OFF_M1, H1, N_NODES, HDIM, H2DIM,
        nullptr, nullptr, nullptr, SUM + 128, SQ + 128);
    bn_finalize_kernel<<<2, 128>>>(g1, b1, 128, 256, 1.f / (float)N_NODES);

    // MLP layer 2
    gemm_mma_kernel<<<dim3(MBLK, 2), 256, GEMM_SMEM>>>(
        H1, WB + OFF_M2, H2, N_NODES, H2DIM, H2DIM,
        SCALE + 128, SHIFT + 128, nullptr, SUM + 384, SQ + 384);
    bn_finalize_kernel<<<2, 128>>>(g2, b2, 384, 256, 1.f / (float)N_NODES);

    // MLP layer 3
    gemm_mma_kernel<<<dim3(MBLK, 1), 256, GEMM_SMEM>>>(
        H2, WB + OFF_M3, out, N_NODES, H2DIM, HDIM,
        SCALE + 384, SHIFT + 384, bm3, nullptr, nullptr);
}